// round 5
// baseline (speedup 1.0000x reference)
#include <cuda_runtime.h>
#include <cuda_fp16.h>
#include <math.h>

#define Nn    50000
#define NPAD  50048            // 782 * 64
#define Ee    1600000
#define F     128
#define ALPHA 0.2f

// ---------------- scratch (static device globals; no allocation) -------------
__device__ __half d_Wh[F * F];        // fp16 copy of W
__device__ __half d_hwh[NPAD * F];    // fp16 hw = h @ W
__device__ float  d_wa_src[F];        // W @ a_src
__device__ float  d_wa_dst[F];        // W @ a_dst
__device__ float  d_ssrc[Nn];
__device__ float  d_sdst[Nn];
__device__ int    d_rowptr[Nn + 1];

// ---------------- PTX helpers ------------------------------------------------
__device__ __forceinline__ unsigned s2u(const void* p) {
    return (unsigned)__cvta_generic_to_shared(p);
}
__device__ __forceinline__ void ldsm_x4(unsigned& r0, unsigned& r1,
                                        unsigned& r2, unsigned& r3, unsigned a) {
    asm volatile("ldmatrix.sync.aligned.m8n8.x4.shared.b16 {%0,%1,%2,%3}, [%4];"
                 : "=r"(r0), "=r"(r1), "=r"(r2), "=r"(r3) : "r"(a));
}
__device__ __forceinline__ void ldsm_x4_t(unsigned& r0, unsigned& r1,
                                          unsigned& r2, unsigned& r3, unsigned a) {
    asm volatile("ldmatrix.sync.aligned.m8n8.x4.trans.shared.b16 {%0,%1,%2,%3}, [%4];"
                 : "=r"(r0), "=r"(r1), "=r"(r2), "=r"(r3) : "r"(a));
}
__device__ __forceinline__ void mma16816(float* c, const unsigned* a,
                                         unsigned b0, unsigned b1) {
    asm volatile(
        "mma.sync.aligned.m16n8k16.row.col.f32.f16.f16.f32 "
        "{%0,%1,%2,%3},{%4,%5,%6,%7},{%8,%9},{%0,%1,%2,%3};"
        : "+f"(c[0]), "+f"(c[1]), "+f"(c[2]), "+f"(c[3])
        : "r"(a[0]), "r"(a[1]), "r"(a[2]), "r"(a[3]), "r"(b0), "r"(b1));
}

// =============================================================================
// K0: blocks 0..15 convert W -> fp16; block 16: wa_src/wa_dst = W @ a
// =============================================================================
__global__ void prep_kernel(const float* __restrict__ W,
                            const float* __restrict__ a_src,
                            const float* __restrict__ a_dst) {
    const int b = blockIdx.x, t = threadIdx.x;
    if (b < 16) {
        int base = b * 1024 + t * 4;
        float4 v = __ldg(&reinterpret_cast<const float4*>(W)[base >> 2]);
        __half2 p0 = __float22half2_rn(make_float2(v.x, v.y));
        __half2 p1 = __float22half2_rn(make_float2(v.z, v.w));
        uint2 u;
        u.x = *reinterpret_cast<unsigned*>(&p0);
        u.y = *reinterpret_cast<unsigned*>(&p1);
        reinterpret_cast<uint2*>(d_Wh)[base >> 2] = u;
    } else {
        const int w = t >> 5, lane = t & 31;
        float4 a4 = __ldg(&reinterpret_cast<const float4*>(a_src)[lane]);
        float4 d4 = __ldg(&reinterpret_cast<const float4*>(a_dst)[lane]);
        for (int r = w; r < F; r += 8) {
            float4 wv = __ldg(&reinterpret_cast<const float4*>(W)[r * 32 + lane]);
            float ps = wv.x * a4.x + wv.y * a4.y + wv.z * a4.z + wv.w * a4.w;
            float pd = wv.x * d4.x + wv.y * d4.y + wv.z * d4.z + wv.w * d4.w;
            #pragma unroll
            for (int off = 16; off; off >>= 1) {
                ps += __shfl_xor_sync(0xffffffffu, ps, off);
                pd += __shfl_xor_sync(0xffffffffu, pd, off);
            }
            if (lane == 0) { d_wa_src[r] = ps; d_wa_dst[r] = pd; }
        }
    }
}

// =============================================================================
// K1: fused hw = fp16(h) @ fp16(W) (mma.sync) + exact fp32 scores
// =============================================================================
__global__ __launch_bounds__(256) void hgemm_kernel(const float* __restrict__ h) {
    __shared__ __align__(16) __half As[64 * F];    // 16 KB
    __shared__ __align__(16) __half Bs[F * F];     // 32 KB

    const int t       = threadIdx.x;
    const int rowBase = blockIdx.x * 64;
    const int lane    = t & 31;
    const int wid     = t >> 5;
    const int wm      = wid >> 2;
    const int wn      = wid & 3;

    // ---- stage A from fp32 h + exact score partials --------------------------
    {
        const int r   = t >> 2;
        const int seg = t & 3;
        const int gr  = rowBase + r;
        const bool ok = gr < Nn;
        const float4* __restrict__ h4 = reinterpret_cast<const float4*>(h);
        const float4* __restrict__ ws4 = reinterpret_cast<const float4*>(d_wa_src);
        const float4* __restrict__ wd4 = reinterpret_cast<const float4*>(d_wa_dst);
        uint4* __restrict__ As4 = reinterpret_cast<uint4*>(As);

        float ps = 0.f, pd = 0.f;
        #pragma unroll
        for (int j = 0; j < 8; j += 2) {
            float4 v0 = ok ? __ldg(&h4[gr * 32 + seg * 8 + j])     : make_float4(0,0,0,0);
            float4 v1 = ok ? __ldg(&h4[gr * 32 + seg * 8 + j + 1]) : make_float4(0,0,0,0);
            float4 s0 = ws4[seg * 8 + j],     s1 = ws4[seg * 8 + j + 1];
            float4 q0 = wd4[seg * 8 + j],     q1 = wd4[seg * 8 + j + 1];
            ps += v0.x*s0.x + v0.y*s0.y + v0.z*s0.z + v0.w*s0.w
                + v1.x*s1.x + v1.y*s1.y + v1.z*s1.z + v1.w*s1.w;
            pd += v0.x*q0.x + v0.y*q0.y + v0.z*q0.z + v0.w*q0.w
                + v1.x*q1.x + v1.y*q1.y + v1.z*q1.z + v1.w*q1.w;
            __half2 p0 = __float22half2_rn(make_float2(v0.x, v0.y));
            __half2 p1 = __float22half2_rn(make_float2(v0.z, v0.w));
            __half2 p2 = __float22half2_rn(make_float2(v1.x, v1.y));
            __half2 p3 = __float22half2_rn(make_float2(v1.z, v1.w));
            uint4 u;
            u.x = *reinterpret_cast<unsigned*>(&p0);
            u.y = *reinterpret_cast<unsigned*>(&p1);
            u.z = *reinterpret_cast<unsigned*>(&p2);
            u.w = *reinterpret_cast<unsigned*>(&p3);
            int g = seg * 4 + (j >> 1);
            As4[r * 16 + (g ^ (r & 7))] = u;
        }
        ps += __shfl_xor_sync(0xffffffffu, ps, 1);
        ps += __shfl_xor_sync(0xffffffffu, ps, 2);
        pd += __shfl_xor_sync(0xffffffffu, pd, 1);
        pd += __shfl_xor_sync(0xffffffffu, pd, 2);
        if (seg == 0 && ok) { d_ssrc[gr] = ps; d_sdst[gr] = pd; }
    }
    // ---- stage B from fp16 Wh ------------------------------------------------
    {
        const uint4* __restrict__ Wh4 = reinterpret_cast<const uint4*>(d_Wh);
        uint4* __restrict__ Bs4 = reinterpret_cast<uint4*>(Bs);
        #pragma unroll
        for (int i = 0; i < 8; ++i) {
            int G = i * 256 + t;
            int r = G >> 4, g = G & 15;
            Bs4[r * 16 + (g ^ (r & 7))] = Wh4[G];
        }
    }
    __syncthreads();

    const unsigned Ab = s2u(As), Bb = s2u(Bs);
    float c[2][4][4];
    #pragma unroll
    for (int i = 0; i < 2; ++i)
        #pragma unroll
        for (int j = 0; j < 4; ++j)
            #pragma unroll
            for (int q = 0; q < 4; ++q) c[i][j][q] = 0.f;

    #pragma unroll
    for (int kk = 0; kk < 8; ++kk) {
        unsigned a[2][4], b[2][4];
        #pragma unroll
        for (int i = 0; i < 2; ++i) {
            int r = wm * 32 + i * 16 + (lane & 15);
            int g = kk * 2 + (lane >> 4);
            ldsm_x4(a[i][0], a[i][1], a[i][2], a[i][3],
                    Ab + (r * 16 + (g ^ (r & 7))) * 16);
        }
        #pragma unroll
        for (int jp = 0; jp < 2; ++jp) {
            int kr = kk * 16 + (lane & 15);
            int g  = wn * 4 + jp * 2 + (lane >> 4);
            ldsm_x4_t(b[jp][0], b[jp][1], b[jp][2], b[jp][3],
                      Bb + (kr * 16 + (g ^ (kr & 7))) * 16);
        }
        #pragma unroll
        for (int i = 0; i < 2; ++i)
            #pragma unroll
            for (int j = 0; j < 4; ++j)
                mma16816(c[i][j], a[i], b[j >> 1][(j & 1) * 2],
                         b[j >> 1][(j & 1) * 2 + 1]);
    }

    const int g  = lane >> 2;
    const int cp = (lane & 3) * 2;
    #pragma unroll
    for (int i = 0; i < 2; ++i)
        #pragma unroll
        for (int j = 0; j < 4; ++j) {
            int gr = rowBase + wm * 32 + i * 16 + g;
            int gc = wn * 32 + j * 8 + cp;
            __half2 lo = __float22half2_rn(make_float2(c[i][j][0], c[i][j][1]));
            __half2 hi = __float22half2_rn(make_float2(c[i][j][2], c[i][j][3]));
            *reinterpret_cast<__half2*>(&d_hwh[gr * F + gc])       = lo;
            *reinterpret_cast<__half2*>(&d_hwh[(gr + 8) * F + gc]) = hi;
        }
}

// =============================================================================
// K2: edge-parallel rowptr from sorted row
// =============================================================================
__global__ void rowptr_kernel(const int* __restrict__ row) {
    int i = blockIdx.x * blockDim.x + threadIdx.x;
    if (i >= Ee) return;
    int a = __ldg(&row[i]);
    int b = (i + 1 < Ee) ? __ldg(&row[i + 1]) : Nn;
    for (int r = a + 1; r <= b; ++r) d_rowptr[r] = i + 1;
    if (i == 0)
        for (int r = 0; r <= a; ++r) d_rowptr[r] = 0;
}

// =============================================================================
// K3: warp-per-node: online softmax + TENSORIZED gather-aggregate.
// Per 16-edge sub-batch: stage gathered fp16 rows into a per-warp 4KB swizzled
// smem tile, then D(16x8 per group) += A(weights, all rows equal) @ B(tile)
// via mma.m16n8k16 with fp32 accumulation.  All D rows identical -> row 0.
// =============================================================================
__global__ __launch_bounds__(256) void edge_kernel(const int* __restrict__ col,
                                                   float* __restrict__ out) {
    __shared__ __align__(16) __half s_tile[8][16 * F];   // 4KB per warp
    const int warp = threadIdx.x >> 5;
    const int lane = threadIdx.x & 31;
    const int gw   = (blockIdx.x * blockDim.x + threadIdx.x) >> 5;
    if (gw >= Nn) return;

    const int   eb   = d_rowptr[gw];
    const int   ee   = d_rowptr[gw + 1];
    const float ssrc = d_ssrc[gw];

    uint4* __restrict__ tile4 = reinterpret_cast<uint4*>(s_tile[warp]);
    const unsigned smb = s2u(s_tile[warp]);
    const uint4* __restrict__ hw4 = reinterpret_cast<const uint4*>(d_hwh);

    const int tig  = lane & 3;                         // thread-in-group
    const int kidx = ((lane >> 3) & 1) * 8 + (lane & 7);  // ldmatrix row (k)
    const int joff = lane >> 4;                        // ldmatrix feature-group pair

    float c[16][4];
    #pragma unroll
    for (int j = 0; j < 16; ++j)
        #pragma unroll
        for (int q = 0; q < 4; ++q) c[j][q] = 0.f;

    float m = -1e30f, sum = 0.f;

    for (int e0 = eb; e0 < ee; e0 += 32) {
        const int e   = e0 + lane;
        const int cnt = min(32, ee - e0);

        // ---- per-lane score + online softmax state ---------------------------
        float v = -1e30f; int cl = 0;
        if (e < ee) {
            cl = __ldg(&col[e]);
            float s = ssrc + __ldg(&d_sdst[cl]);
            v = (s > 0.f) ? s : ALPHA * s;
        }
        float bm = v;
        #pragma unroll
        for (int off = 16; off; off >>= 1)
            bm = fmaxf(bm, __shfl_xor_sync(0xffffffffu, bm, off));
        if (bm > m) {
            const float sc = __expf(m - bm);
            sum *= sc;
            #pragma unroll
            for (int j = 0; j < 16; ++j) {
                c[j][0] *= sc; c[j][1] *= sc; c[j][2] *= sc; c[j][3] *= sc;
            }
            m = bm;
        }
        float wl = __expf(v - m);
        wl = __half2float(__float2half_rn(wl));   // quantize: numerator == fp16 A
        float bs = wl;
        #pragma unroll
        for (int off = 16; off; off >>= 1)
            bs += __shfl_xor_sync(0xffffffffu, bs, off);
        sum += bs;

        // ---- two 16-edge sub-batches -----------------------------------------
        #pragma unroll
        for (int sb = 0; sb < 2; ++sb) {
            const int base = sb * 16;
            if (base >= cnt) break;

            // stage 16 gathered rows (zeros for invalid edges)
            #pragma unroll
            for (int it = 0; it < 8; ++it) {
                const int kl = 2 * it + (lane >> 4);
                const int g  = lane & 15;
                const int cc = __shfl_sync(0xffffffffu, cl, base + kl);
                uint4 q = make_uint4(0u, 0u, 0u, 0u);
                if (base + kl < cnt) q = __ldg(&hw4[cc * 16 + g]);
                tile4[kl * 16 + (g ^ (kl & 7))] = q;
            }
            __syncwarp();

            // A fragment: A[r][k] = w[k] for all r
            const float w0 = __shfl_sync(0xffffffffu, wl, base + tig * 2);
            const float w1 = __shfl_sync(0xffffffffu, wl, base + tig * 2 + 1);
            const float w8 = __shfl_sync(0xffffffffu, wl, base + tig * 2 + 8);
            const float w9 = __shfl_sync(0xffffffffu, wl, base + tig * 2 + 9);
            __half2 h01 = __floats2half2_rn(w0, w1);
            __half2 h89 = __floats2half2_rn(w8, w9);
            unsigned a01 = *reinterpret_cast<unsigned*>(&h01);
            unsigned a89 = *reinterpret_cast<unsigned*>(&h89);
            unsigned afrag[4] = {a01, a01, a89, a89};

            // 8 ldmatrix.x4.trans + 16 HMMA cover all 128 features
            #pragma unroll
            for (int j = 0; j < 16; j += 2) {
                unsigned addr = smb +
                    (kidx * 16 + ((j + joff) ^ (kidx & 7))) * 16;
                unsigned b0, b1, b2, b3;
                ldsm_x4_t(b0, b1, b2, b3, addr);
                mma16816(c[j],     afrag, b0, b1);
                mma16816(c[j + 1], afrag, b2, b3);
            }
            __syncwarp();
        }
    }

    // ---- epilogue: row 0 of D -> smem -> normalized elu output ---------------
    const float inv = (ee > eb) ? (1.f / sum) : 0.f;
    __syncwarp();
    float* fbuf = reinterpret_cast<float*>(s_tile[warp]);
    if ((lane >> 2) == 0) {                 // lanes 0..3 hold row 0
        #pragma unroll
        for (int j = 0; j < 16; ++j)
            reinterpret_cast<float2*>(fbuf)[j * 4 + tig] =
                make_float2(c[j][0], c[j][1]);
    }
    __syncwarp();
    float4 vv = reinterpret_cast<float4*>(fbuf)[lane];
    float4 o;
    float x;
    x = vv.x * inv; o.x = (x > 0.f) ? x : expm1f(x);
    x = vv.y * inv; o.y = (x > 0.f) ? x : expm1f(x);
    x = vv.z * inv; o.z = (x > 0.f) ? x : expm1f(x);
    x = vv.w * inv; o.w = (x > 0.f) ? x : expm1f(x);
    reinterpret_cast<float4*>(&out[gw * F])[lane] = o;
}

// =============================================================================
extern "C" void kernel_launch(void* const* d_in, const int* in_sizes, int n_in,
                              void* d_out, int out_size) {
    const float* h     = (const float*)d_in[0];
    const float* W     = (const float*)d_in[1];
    const float* a_src = (const float*)d_in[2];
    const float* a_dst = (const float*)d_in[3];
    const int*   row   = (const int*)d_in[4];
    const int*   col   = (const int*)d_in[5];
    float*       out   = (float*)d_out;

    prep_kernel<<<17, 256>>>(W, a_src, a_dst);
    hgemm_kernel<<<NPAD / 64, 256>>>(h);
    rowptr_kernel<<<(Ee + 255) / 256, 256>>>(row);
    edge_kernel<<<(Nn * 32 + 255) / 256, 256>>>(col, out);
}

// round 6
// speedup vs baseline: 1.3985x; 1.3985x over previous
#include <cuda_runtime.h>
#include <cuda_fp16.h>
#include <math.h>

#define Nn    50000
#define NPAD  50048            // 782 * 64
#define Ee    1600000
#define F     128
#define ALPHA 0.2f

// ---------------- scratch (static device globals; no allocation) -------------
__device__ __half d_Wh[F * F];        // fp16 copy of W
__device__ __half d_hwh[NPAD * F];    // fp16 hw = h @ W
__device__ float  d_wa_src[F];        // W @ a_src
__device__ float  d_wa_dst[F];        // W @ a_dst
__device__ float  d_ssrc[Nn];
__device__ float  d_sdst[Nn];
__device__ int    d_rowptr[Nn + 1];
__device__ float  d_sc[Ee];           // per-edge pre-softmax score v
__device__ __half d_ew[Ee];           // per-edge fp16 weight exp(v - m)

// ---------------- PTX helpers ------------------------------------------------
__device__ __forceinline__ unsigned s2u(const void* p) {
    return (unsigned)__cvta_generic_to_shared(p);
}
__device__ __forceinline__ void ldsm_x4(unsigned& r0, unsigned& r1,
                                        unsigned& r2, unsigned& r3, unsigned a) {
    asm volatile("ldmatrix.sync.aligned.m8n8.x4.shared.b16 {%0,%1,%2,%3}, [%4];"
                 : "=r"(r0), "=r"(r1), "=r"(r2), "=r"(r3) : "r"(a));
}
__device__ __forceinline__ void ldsm_x4_t(unsigned& r0, unsigned& r1,
                                          unsigned& r2, unsigned& r3, unsigned a) {
    asm volatile("ldmatrix.sync.aligned.m8n8.x4.trans.shared.b16 {%0,%1,%2,%3}, [%4];"
                 : "=r"(r0), "=r"(r1), "=r"(r2), "=r"(r3) : "r"(a));
}
__device__ __forceinline__ void mma16816(float* c, const unsigned* a,
                                         unsigned b0, unsigned b1) {
    asm volatile(
        "mma.sync.aligned.m16n8k16.row.col.f32.f16.f16.f32 "
        "{%0,%1,%2,%3},{%4,%5,%6,%7},{%8,%9},{%0,%1,%2,%3};"
        : "+f"(c[0]), "+f"(c[1]), "+f"(c[2]), "+f"(c[3])
        : "r"(a[0]), "r"(a[1]), "r"(a[2]), "r"(a[3]), "r"(b0), "r"(b1));
}
__device__ __forceinline__ void cp16(unsigned dst, const void* src, int sz) {
    asm volatile("cp.async.ca.shared.global [%0], [%1], 16, %2;"
                 :: "r"(dst), "l"(src), "r"(sz) : "memory");
}
__device__ __forceinline__ void cp_commit() {
    asm volatile("cp.async.commit_group;" ::: "memory");
}
__device__ __forceinline__ void cp_wait1() {
    asm volatile("cp.async.wait_group 1;" ::: "memory");
}
__device__ __forceinline__ void cp_wait0() {
    asm volatile("cp.async.wait_group 0;" ::: "memory");
}

// =============================================================================
// K0: blocks 0..15 convert W -> fp16; block 16: wa_src/wa_dst = W @ a
// =============================================================================
__global__ void prep_kernel(const float* __restrict__ W,
                            const float* __restrict__ a_src,
                            const float* __restrict__ a_dst) {
    const int b = blockIdx.x, t = threadIdx.x;
    if (b < 16) {
        int base = b * 1024 + t * 4;
        float4 v = __ldg(&reinterpret_cast<const float4*>(W)[base >> 2]);
        __half2 p0 = __float22half2_rn(make_float2(v.x, v.y));
        __half2 p1 = __float22half2_rn(make_float2(v.z, v.w));
        uint2 u;
        u.x = *reinterpret_cast<unsigned*>(&p0);
        u.y = *reinterpret_cast<unsigned*>(&p1);
        reinterpret_cast<uint2*>(d_Wh)[base >> 2] = u;
    } else {
        const int w = t >> 5, lane = t & 31;
        float4 a4 = __ldg(&reinterpret_cast<const float4*>(a_src)[lane]);
        float4 d4 = __ldg(&reinterpret_cast<const float4*>(a_dst)[lane]);
        for (int r = w; r < F; r += 8) {
            float4 wv = __ldg(&reinterpret_cast<const float4*>(W)[r * 32 + lane]);
            float ps = wv.x * a4.x + wv.y * a4.y + wv.z * a4.z + wv.w * a4.w;
            float pd = wv.x * d4.x + wv.y * d4.y + wv.z * d4.z + wv.w * d4.w;
            #pragma unroll
            for (int off = 16; off; off >>= 1) {
                ps += __shfl_xor_sync(0xffffffffu, ps, off);
                pd += __shfl_xor_sync(0xffffffffu, pd, off);
            }
            if (lane == 0) { d_wa_src[r] = ps; d_wa_dst[r] = pd; }
        }
    }
}

// =============================================================================
// K1: fused hw = fp16(h) @ fp16(W) (mma.sync) + exact fp32 scores
// =============================================================================
__global__ __launch_bounds__(256) void hgemm_kernel(const float* __restrict__ h) {
    __shared__ __align__(16) __half As[64 * F];    // 16 KB
    __shared__ __align__(16) __half Bs[F * F];     // 32 KB

    const int t       = threadIdx.x;
    const int rowBase = blockIdx.x * 64;
    const int lane    = t & 31;
    const int wid     = t >> 5;
    const int wm      = wid >> 2;
    const int wn      = wid & 3;

    // ---- stage A from fp32 h + exact score partials --------------------------
    {
        const int r   = t >> 2;
        const int seg = t & 3;
        const int gr  = rowBase + r;
        const bool ok = gr < Nn;
        const float4* __restrict__ h4 = reinterpret_cast<const float4*>(h);
        const float4* __restrict__ ws4 = reinterpret_cast<const float4*>(d_wa_src);
        const float4* __restrict__ wd4 = reinterpret_cast<const float4*>(d_wa_dst);
        uint4* __restrict__ As4 = reinterpret_cast<uint4*>(As);

        float ps = 0.f, pd = 0.f;
        #pragma unroll
        for (int j = 0; j < 8; j += 2) {
            float4 v0 = ok ? __ldg(&h4[gr * 32 + seg * 8 + j])     : make_float4(0,0,0,0);
            float4 v1 = ok ? __ldg(&h4[gr * 32 + seg * 8 + j + 1]) : make_float4(0,0,0,0);
            float4 s0 = ws4[seg * 8 + j],     s1 = ws4[seg * 8 + j + 1];
            float4 q0 = wd4[seg * 8 + j],     q1 = wd4[seg * 8 + j + 1];
            ps += v0.x*s0.x + v0.y*s0.y + v0.z*s0.z + v0.w*s0.w
                + v1.x*s1.x + v1.y*s1.y + v1.z*s1.z + v1.w*s1.w;
            pd += v0.x*q0.x + v0.y*q0.y + v0.z*q0.z + v0.w*q0.w
                + v1.x*q1.x + v1.y*q1.y + v1.z*q1.z + v1.w*q1.w;
            __half2 p0 = __float22half2_rn(make_float2(v0.x, v0.y));
            __half2 p1 = __float22half2_rn(make_float2(v0.z, v0.w));
            __half2 p2 = __float22half2_rn(make_float2(v1.x, v1.y));
            __half2 p3 = __float22half2_rn(make_float2(v1.z, v1.w));
            uint4 u;
            u.x = *reinterpret_cast<unsigned*>(&p0);
            u.y = *reinterpret_cast<unsigned*>(&p1);
            u.z = *reinterpret_cast<unsigned*>(&p2);
            u.w = *reinterpret_cast<unsigned*>(&p3);
            int g = seg * 4 + (j >> 1);
            As4[r * 16 + (g ^ (r & 7))] = u;
        }
        ps += __shfl_xor_sync(0xffffffffu, ps, 1);
        ps += __shfl_xor_sync(0xffffffffu, ps, 2);
        pd += __shfl_xor_sync(0xffffffffu, pd, 1);
        pd += __shfl_xor_sync(0xffffffffu, pd, 2);
        if (seg == 0 && ok) { d_ssrc[gr] = ps; d_sdst[gr] = pd; }
    }
    // ---- stage B from fp16 Wh ------------------------------------------------
    {
        const uint4* __restrict__ Wh4 = reinterpret_cast<const uint4*>(d_Wh);
        uint4* __restrict__ Bs4 = reinterpret_cast<uint4*>(Bs);
        #pragma unroll
        for (int i = 0; i < 8; ++i) {
            int G = i * 256 + t;
            int r = G >> 4, g = G & 15;
            Bs4[r * 16 + (g ^ (r & 7))] = Wh4[G];
        }
    }
    __syncthreads();

    const unsigned Ab = s2u(As), Bb = s2u(Bs);
    float c[2][4][4];
    #pragma unroll
    for (int i = 0; i < 2; ++i)
        #pragma unroll
        for (int j = 0; j < 4; ++j)
            #pragma unroll
            for (int q = 0; q < 4; ++q) c[i][j][q] = 0.f;

    #pragma unroll
    for (int kk = 0; kk < 8; ++kk) {
        unsigned a[2][4], b[2][4];
        #pragma unroll
        for (int i = 0; i < 2; ++i) {
            int r = wm * 32 + i * 16 + (lane & 15);
            int g = kk * 2 + (lane >> 4);
            ldsm_x4(a[i][0], a[i][1], a[i][2], a[i][3],
                    Ab + (r * 16 + (g ^ (r & 7))) * 16);
        }
        #pragma unroll
        for (int jp = 0; jp < 2; ++jp) {
            int kr = kk * 16 + (lane & 15);
            int g  = wn * 4 + jp * 2 + (lane >> 4);
            ldsm_x4_t(b[jp][0], b[jp][1], b[jp][2], b[jp][3],
                      Bb + (kr * 16 + (g ^ (kr & 7))) * 16);
        }
        #pragma unroll
        for (int i = 0; i < 2; ++i)
            #pragma unroll
            for (int j = 0; j < 4; ++j)
                mma16816(c[i][j], a[i], b[j >> 1][(j & 1) * 2],
                         b[j >> 1][(j & 1) * 2 + 1]);
    }

    const int g  = lane >> 2;
    const int cp = (lane & 3) * 2;
    #pragma unroll
    for (int i = 0; i < 2; ++i)
        #pragma unroll
        for (int j = 0; j < 4; ++j) {
            int gr = rowBase + wm * 32 + i * 16 + g;
            int gc = wn * 32 + j * 8 + cp;
            __half2 lo = __float22half2_rn(make_float2(c[i][j][0], c[i][j][1]));
            __half2 hi = __float22half2_rn(make_float2(c[i][j][2], c[i][j][3]));
            *reinterpret_cast<__half2*>(&d_hwh[gr * F + gc])       = lo;
            *reinterpret_cast<__half2*>(&d_hwh[(gr + 8) * F + gc]) = hi;
        }
}

// =============================================================================
// K2: edge-parallel rowptr from sorted row
// =============================================================================
__global__ void rowptr_kernel(const int* __restrict__ row) {
    int i = blockIdx.x * blockDim.x + threadIdx.x;
    if (i >= Ee) return;
    int a = __ldg(&row[i]);
    int b = (i + 1 < Ee) ? __ldg(&row[i + 1]) : Nn;
    for (int r = a + 1; r <= b; ++r) d_rowptr[r] = i + 1;
    if (i == 0)
        for (int r = 0; r <= a; ++r) d_rowptr[r] = 0;
}

// =============================================================================
// K3: warp-per-node, two-pass softmax + cp.async double-buffered HMMA gather.
//   Pass A: sweep1 max (store v), sweep2 fp16 weights wq + sum(wq).
//   Pass B: per 16-edge batch, cp.async gathered rows into per-warp swizzled
//   smem (2 buffers), A = broadcast weight row, 16x HMMA fp32-acc; D row 0.
// =============================================================================
__global__ __launch_bounds__(128) void edge_kernel(const int* __restrict__ col,
                                                   float* __restrict__ out) {
    __shared__ __align__(16) __half s_tile[4][2][16 * F];   // 4 warps x 2 x 4KB
    const int warp = threadIdx.x >> 5;
    const int lane = threadIdx.x & 31;
    const int gw   = (blockIdx.x * blockDim.x + threadIdx.x) >> 5;
    if (gw >= Nn) return;

    const int   eb   = d_rowptr[gw];
    const int   ee   = d_rowptr[gw + 1];
    const float ssrc = d_ssrc[gw];

    // ---- pass A: sweep1 (scores + max) ---------------------------------------
    float m = -1e30f;
    for (int e0 = eb; e0 < ee; e0 += 32) {
        int e = e0 + lane;
        float v = -1e30f;
        if (e < ee) {
            int cl = __ldg(&col[e]);
            float s = ssrc + __ldg(&d_sdst[cl]);
            v = (s > 0.f) ? s : ALPHA * s;
            d_sc[e] = v;
        }
        m = fmaxf(m, v);
    }
    #pragma unroll
    for (int off = 16; off; off >>= 1)
        m = fmaxf(m, __shfl_xor_sync(0xffffffffu, m, off));

    // ---- pass A: sweep2 (fp16 weights + consistent sum) ----------------------
    float sum = 0.f;
    for (int e0 = eb; e0 < ee; e0 += 32) {
        int e = e0 + lane;
        if (e < ee) {
            float v = d_sc[e];
            __half hq = __float2half_rn(__expf(v - m));
            d_ew[e] = hq;
            sum += __half2float(hq);
        }
    }
    #pragma unroll
    for (int off = 16; off; off >>= 1)
        sum += __shfl_xor_sync(0xffffffffu, sum, off);
    const float inv = (ee > eb) ? (1.f / sum) : 0.f;

    __threadfence_block();
    __syncwarp();

    // ---- pass B: double-buffered cp.async + HMMA -----------------------------
    const unsigned sm0 = s2u(s_tile[warp][0]);
    const unsigned sm1 = s2u(s_tile[warp][1]);
    const char* __restrict__ hwb = reinterpret_cast<const char*>(d_hwh);

    const int nb   = (ee - eb + 15) >> 4;
    const int tig  = lane & 3;
    const int kidx = ((lane >> 3) & 1) * 8 + (lane & 7);
    const int joff = lane >> 4;
    const int gsl  = lane & 15;          // granule slot for cp.async
    const int klh  = lane >> 4;          // 0/1: which of the 2 rows per it

    float c[16][4];
    #pragma unroll
    for (int j = 0; j < 16; ++j)
        #pragma unroll
        for (int q = 0; q < 4; ++q) c[j][q] = 0.f;

    int      cc_cur = 0, cc_nxt = 0;
    unsigned wq_cur = 0, wq_nxt = 0;

    // meta(b): lanes' (lane&15) slot of batch b
    #define META(b, CC, WQ) do {                                              \
        int e_ = eb + (b) * 16 + (lane & 15);                                 \
        if (e_ < ee) {                                                        \
            CC = __ldg(&col[e_]);                                             \
            WQ = (unsigned)*reinterpret_cast<const unsigned short*>(&d_ew[e_]);\
        } else { CC = 0; WQ = 0u; }                                           \
    } while (0)

    #define ISSUE(b, CC, DSTB) do {                                           \
        const int rem_ = ee - (eb + (b) * 16);                                \
        _Pragma("unroll")                                                     \
        for (int it = 0; it < 8; ++it) {                                      \
            int kl_ = klh + 2 * it;                                           \
            int cck_ = __shfl_sync(0xffffffffu, CC, kl_);                     \
            int sz_  = (kl_ < rem_) ? 16 : 0;                                 \
            unsigned dst_ = (DSTB) + (unsigned)((kl_ * 16 + (gsl ^ (kl_ & 7))) * 16); \
            cp16(dst_, hwb + ((long long)cck_ * 256 + gsl * 16), sz_);        \
        }                                                                     \
        cp_commit();                                                          \
    } while (0)

    if (nb > 0) {
        META(0, cc_cur, wq_cur);
        ISSUE(0, cc_cur, sm0);
    }
    for (int b = 0; b < nb; ++b) {
        if (b + 1 < nb) {
            META(b + 1, cc_nxt, wq_nxt);
            ISSUE(b + 1, cc_nxt, ((b + 1) & 1) ? sm1 : sm0);
            cp_wait1();
        } else {
            cp_wait0();
        }
        __syncwarp();

        // A fragment: all 16 rows equal the weight vector
        unsigned w0 = __shfl_sync(0xffffffffu, wq_cur, tig * 2);
        unsigned w1 = __shfl_sync(0xffffffffu, wq_cur, tig * 2 + 1);
        unsigned w8 = __shfl_sync(0xffffffffu, wq_cur, tig * 2 + 8);
        unsigned w9 = __shfl_sync(0xffffffffu, wq_cur, tig * 2 + 9);
        unsigned a01 = (w0 & 0xffffu) | (w1 << 16);
        unsigned a89 = (w8 & 0xffffu) | (w9 << 16);
        unsigned af[4] = {a01, a01, a89, a89};

        const unsigned smb = (b & 1) ? sm1 : sm0;
        #pragma unroll
        for (int j = 0; j < 16; j += 2) {
            unsigned addr = smb + (kidx * 16 + ((j + joff) ^ (kidx & 7))) * 16;
            unsigned b0, b1, b2, b3;
            ldsm_x4_t(b0, b1, b2, b3, addr);
            mma16816(c[j],     af, b0, b1);
            mma16816(c[j + 1], af, b2, b3);
        }
        cc_cur = cc_nxt; wq_cur = wq_nxt;
        __syncwarp();
    }

    // ---- epilogue: row 0 of D -> smem -> normalized elu output ---------------
    __syncwarp();
    float* fbuf = reinterpret_cast<float*>(s_tile[warp][0]);
    if ((lane >> 2) == 0) {                 // lanes 0..3 hold row 0
        #pragma unroll
        for (int j = 0; j < 16; ++j)
            reinterpret_cast<float2*>(fbuf)[j * 4 + tig] =
                make_float2(c[j][0], c[j][1]);
    }
    __syncwarp();
    float4 vv = reinterpret_cast<float4*>(fbuf)[lane];
    float4 o;
    float x;
    x = vv.x * inv; o.x = (x > 0.f) ? x : expm1f(x);
    x = vv.y * inv; o.y = (x > 0.f) ? x : expm1f(x);
    x = vv.z * inv; o.z = (x > 0.f) ? x : expm1f(x);
    x = vv.w * inv; o.w = (x > 0.f) ? x : expm1f(x);
    reinterpret_cast<float4*>(&out[gw * F])[lane] = o;
    #undef META
    #undef ISSUE
}

// =============================================================================
extern "C" void kernel_launch(void* const* d_in, const int* in_sizes, int n_in,
                              void* d_out, int out_size) {
    const float* h     = (const float*)d_in[0];
    const float* W     = (const float*)d_in[1];
    const float* a_src = (const float*)d_in[2];
    const float* a_dst = (const float*)d_in[3];
    const int*   row   = (const int*)d_in[4];
    const int*   col   = (const int*)d_in[5];
    float*       out   = (float*)d_out;

    prep_kernel<<<17, 256>>>(W, a_src, a_dst);
    hgemm_kernel<<<NPAD / 64, 256>>>(h);
    rowptr_kernel<<<(Ee + 255) / 256, 256>>>(row);
    edge_kernel<<<(Nn * 32 + 127) / 128, 128>>>(col, out);
}

// round 8
// speedup vs baseline: 1.4752x; 1.0549x over previous
#include <cuda_runtime.h>
#include <cuda_fp16.h>
#include <math.h>

#define Nn    50000
#define NPAD  50048            // 782 * 64
#define Ee    1600000
#define F     128
#define ALPHA 0.2f
#define NW    3125             // Nn / 16 node windows

// ---------------- scratch (static device globals; no allocation) -------------
__device__ __half d_Wh[F * F];        // fp16 copy of W
__device__ __half d_hwh[NPAD * F];    // fp16 hw = h @ W
__device__ float  d_wa_src[F];        // W @ a_src
__device__ float  d_wa_dst[F];        // W @ a_dst
__device__ float  d_ssrc[Nn];
__device__ float  d_sdst[Nn];
__device__ float  d_inv[Nn];          // 1 / softmax denom
__device__ int    d_rowptr[Nn + 1];
__device__ __half d_ew[Ee];           // per-edge fp16 weight exp(v - m)

// ---------------- PTX helpers ------------------------------------------------
__device__ __forceinline__ unsigned s2u(const void* p) {
    return (unsigned)__cvta_generic_to_shared(p);
}
__device__ __forceinline__ void ldsm_x4(unsigned& r0, unsigned& r1,
                                        unsigned& r2, unsigned& r3, unsigned a) {
    asm volatile("ldmatrix.sync.aligned.m8n8.x4.shared.b16 {%0,%1,%2,%3}, [%4];"
                 : "=r"(r0), "=r"(r1), "=r"(r2), "=r"(r3) : "r"(a));
}
__device__ __forceinline__ void ldsm_x4_t(unsigned& r0, unsigned& r1,
                                          unsigned& r2, unsigned& r3, unsigned a) {
    asm volatile("ldmatrix.sync.aligned.m8n8.x4.trans.shared.b16 {%0,%1,%2,%3}, [%4];"
                 : "=r"(r0), "=r"(r1), "=r"(r2), "=r"(r3) : "r"(a));
}
__device__ __forceinline__ void mma16816(float* c, const unsigned* a,
                                         unsigned b0, unsigned b1) {
    asm volatile(
        "mma.sync.aligned.m16n8k16.row.col.f32.f16.f16.f32 "
        "{%0,%1,%2,%3},{%4,%5,%6,%7},{%8,%9},{%0,%1,%2,%3};"
        : "+f"(c[0]), "+f"(c[1]), "+f"(c[2]), "+f"(c[3])
        : "r"(a[0]), "r"(a[1]), "r"(a[2]), "r"(a[3]), "r"(b0), "r"(b1));
}
__device__ __forceinline__ void cp16(unsigned dst, const void* src, int sz) {
    asm volatile("cp.async.ca.shared.global [%0], [%1], 16, %2;"
                 :: "r"(dst), "l"(src), "r"(sz) : "memory");
}
__device__ __forceinline__ void cp_commit() {
    asm volatile("cp.async.commit_group;" ::: "memory");
}
__device__ __forceinline__ void cp_wait2() {
    asm volatile("cp.async.wait_group 2;" ::: "memory");
}
__device__ __forceinline__ void cp_wait0() {
    asm volatile("cp.async.wait_group 0;" ::: "memory");
}

// =============================================================================
// K0: blocks 0..15 convert W -> fp16; block 16: wa_src/wa_dst = W @ a
// =============================================================================
__global__ void prep_kernel(const float* __restrict__ W,
                            const float* __restrict__ a_src,
                            const float* __restrict__ a_dst) {
    const int b = blockIdx.x, t = threadIdx.x;
    if (b < 16) {
        int base = b * 1024 + t * 4;
        float4 v = __ldg(&reinterpret_cast<const float4*>(W)[base >> 2]);
        __half2 p0 = __float22half2_rn(make_float2(v.x, v.y));
        __half2 p1 = __float22half2_rn(make_float2(v.z, v.w));
        uint2 u;
        u.x = *reinterpret_cast<unsigned*>(&p0);
        u.y = *reinterpret_cast<unsigned*>(&p1);
        reinterpret_cast<uint2*>(d_Wh)[base >> 2] = u;
    } else {
        const int w = t >> 5, lane = t & 31;
        float4 a4 = __ldg(&reinterpret_cast<const float4*>(a_src)[lane]);
        float4 d4 = __ldg(&reinterpret_cast<const float4*>(a_dst)[lane]);
        for (int r = w; r < F; r += 8) {
            float4 wv = __ldg(&reinterpret_cast<const float4*>(W)[r * 32 + lane]);
            float ps = wv.x * a4.x + wv.y * a4.y + wv.z * a4.z + wv.w * a4.w;
            float pd = wv.x * d4.x + wv.y * d4.y + wv.z * d4.z + wv.w * d4.w;
            #pragma unroll
            for (int off = 16; off; off >>= 1) {
                ps += __shfl_xor_sync(0xffffffffu, ps, off);
                pd += __shfl_xor_sync(0xffffffffu, pd, off);
            }
            if (lane == 0) { d_wa_src[r] = ps; d_wa_dst[r] = pd; }
        }
    }
}

// =============================================================================
// K1: fused hw = fp16(h) @ fp16(W) (mma.sync) + exact fp32 scores
// =============================================================================
__global__ __launch_bounds__(256) void hgemm_kernel(const float* __restrict__ h) {
    __shared__ __align__(16) __half As[64 * F];    // 16 KB
    __shared__ __align__(16) __half Bs[F * F];     // 32 KB

    const int t       = threadIdx.x;
    const int rowBase = blockIdx.x * 64;
    const int lane    = t & 31;
    const int wid     = t >> 5;
    const int wm      = wid >> 2;
    const int wn      = wid & 3;

    {
        const int r   = t >> 2;
        const int seg = t & 3;
        const int gr  = rowBase + r;
        const bool ok = gr < Nn;
        const float4* __restrict__ h4 = reinterpret_cast<const float4*>(h);
        const float4* __restrict__ ws4 = reinterpret_cast<const float4*>(d_wa_src);
        const float4* __restrict__ wd4 = reinterpret_cast<const float4*>(d_wa_dst);
        uint4* __restrict__ As4 = reinterpret_cast<uint4*>(As);

        float ps = 0.f, pd = 0.f;
        #pragma unroll
        for (int j = 0; j < 8; j += 2) {
            float4 v0 = ok ? __ldg(&h4[gr * 32 + seg * 8 + j])     : make_float4(0,0,0,0);
            float4 v1 = ok ? __ldg(&h4[gr * 32 + seg * 8 + j + 1]) : make_float4(0,0,0,0);
            float4 s0 = ws4[seg * 8 + j],     s1 = ws4[seg * 8 + j + 1];
            float4 q0 = wd4[seg * 8 + j],     q1 = wd4[seg * 8 + j + 1];
            ps += v0.x*s0.x + v0.y*s0.y + v0.z*s0.z + v0.w*s0.w
                + v1.x*s1.x + v1.y*s1.y + v1.z*s1.z + v1.w*s1.w;
            pd += v0.x*q0.x + v0.y*q0.y + v0.z*q0.z + v0.w*q0.w
                + v1.x*q1.x + v1.y*q1.y + v1.z*q1.z + v1.w*q1.w;
            __half2 p0 = __float22half2_rn(make_float2(v0.x, v0.y));
            __half2 p1 = __float22half2_rn(make_float2(v0.z, v0.w));
            __half2 p2 = __float22half2_rn(make_float2(v1.x, v1.y));
            __half2 p3 = __float22half2_rn(make_float2(v1.z, v1.w));
            uint4 u;
            u.x = *reinterpret_cast<unsigned*>(&p0);
            u.y = *reinterpret_cast<unsigned*>(&p1);
            u.z = *reinterpret_cast<unsigned*>(&p2);
            u.w = *reinterpret_cast<unsigned*>(&p3);
            int g = seg * 4 + (j >> 1);
            As4[r * 16 + (g ^ (r & 7))] = u;
        }
        ps += __shfl_xor_sync(0xffffffffu, ps, 1);
        ps += __shfl_xor_sync(0xffffffffu, ps, 2);
        pd += __shfl_xor_sync(0xffffffffu, pd, 1);
        pd += __shfl_xor_sync(0xffffffffu, pd, 2);
        if (seg == 0 && ok) { d_ssrc[gr] = ps; d_sdst[gr] = pd; }
    }
    {
        const uint4* __restrict__ Wh4 = reinterpret_cast<const uint4*>(d_Wh);
        uint4* __restrict__ Bs4 = reinterpret_cast<uint4*>(Bs);
        #pragma unroll
        for (int i = 0; i < 8; ++i) {
            int G = i * 256 + t;
            int r = G >> 4, g = G & 15;
            Bs4[r * 16 + (g ^ (r & 7))] = Wh4[G];
        }
    }
    __syncthreads();

    const unsigned Ab = s2u(As), Bb = s2u(Bs);
    float c[2][4][4];
    #pragma unroll
    for (int i = 0; i < 2; ++i)
        #pragma unroll
        for (int j = 0; j < 4; ++j)
            #pragma unroll
            for (int q = 0; q < 4; ++q) c[i][j][q] = 0.f;

    #pragma unroll
    for (int kk = 0; kk < 8; ++kk) {
        unsigned a[2][4], b[2][4];
        #pragma unroll
        for (int i = 0; i < 2; ++i) {
            int r = wm * 32 + i * 16 + (lane & 15);
            int g = kk * 2 + (lane >> 4);
            ldsm_x4(a[i][0], a[i][1], a[i][2], a[i][3],
                    Ab + (r * 16 + (g ^ (r & 7))) * 16);
        }
        #pragma unroll
        for (int jp = 0; jp < 2; ++jp) {
            int kr = kk * 16 + (lane & 15);
            int g  = wn * 4 + jp * 2 + (lane >> 4);
            ldsm_x4_t(b[jp][0], b[jp][1], b[jp][2], b[jp][3],
                      Bb + (kr * 16 + (g ^ (kr & 7))) * 16);
        }
        #pragma unroll
        for (int i = 0; i < 2; ++i)
            #pragma unroll
            for (int j = 0; j < 4; ++j)
                mma16816(c[i][j], a[i], b[j >> 1][(j & 1) * 2],
                         b[j >> 1][(j & 1) * 2 + 1]);
    }

    const int g  = lane >> 2;
    const int cp = (lane & 3) * 2;
    #pragma unroll
    for (int i = 0; i < 2; ++i)
        #pragma unroll
        for (int j = 0; j < 4; ++j) {
            int gr = rowBase + wm * 32 + i * 16 + g;
            int gc = wn * 32 + j * 8 + cp;
            __half2 lo = __float22half2_rn(make_float2(c[i][j][0], c[i][j][1]));
            __half2 hi = __float22half2_rn(make_float2(c[i][j][2], c[i][j][3]));
            *reinterpret_cast<__half2*>(&d_hwh[gr * F + gc])       = lo;
            *reinterpret_cast<__half2*>(&d_hwh[(gr + 8) * F + gc]) = hi;
        }
}

// =============================================================================
// K2: edge-parallel rowptr from sorted row
// =============================================================================
__global__ void rowptr_kernel(const int* __restrict__ row) {
    int i = blockIdx.x * blockDim.x + threadIdx.x;
    if (i >= Ee) return;
    int a = __ldg(&row[i]);
    int b = (i + 1 < Ee) ? __ldg(&row[i + 1]) : Nn;
    for (int r = a + 1; r <= b; ++r) d_rowptr[r] = i + 1;
    if (i == 0)
        for (int r = 0; r <= a; ++r) d_rowptr[r] = 0;
}

// =============================================================================
// K3: pass A — warp-per-node softmax: m, fp16 weights d_ew, d_inv = 1/sum.
// Register path for deg<=64 (covers essentially all nodes), loop fallback else.
// =============================================================================
__global__ __launch_bounds__(256) void score_kernel(const int* __restrict__ col) {
    const int gw   = (blockIdx.x * blockDim.x + threadIdx.x) >> 5;
    const int lane = threadIdx.x & 31;
    if (gw >= Nn) return;
    const int   eb   = d_rowptr[gw];
    const int   ee   = d_rowptr[gw + 1];
    const int   deg  = ee - eb;
    const float ssrc = d_ssrc[gw];

    float sum = 0.f;
    if (deg <= 64) {
        const int e1 = eb + lane, e2 = e1 + 32;
        float v1 = -1e30f, v2 = -1e30f;
        if (e1 < ee) {
            float s = ssrc + __ldg(&d_sdst[__ldg(&col[e1])]);
            v1 = (s > 0.f) ? s : ALPHA * s;
        }
        if (e2 < ee) {
            float s = ssrc + __ldg(&d_sdst[__ldg(&col[e2])]);
            v2 = (s > 0.f) ? s : ALPHA * s;
        }
        float m = fmaxf(v1, v2);
        #pragma unroll
        for (int off = 16; off; off >>= 1)
            m = fmaxf(m, __shfl_xor_sync(0xffffffffu, m, off));
        if (e1 < ee) {
            __half hq = __float2half_rn(__expf(v1 - m));
            d_ew[e1] = hq;
            sum += __half2float(hq);
        }
        if (e2 < ee) {
            __half hq = __float2half_rn(__expf(v2 - m));
            d_ew[e2] = hq;
            sum += __half2float(hq);
        }
    } else {
        float m = -1e30f;
        for (int e0 = eb; e0 < ee; e0 += 32) {
            int e = e0 + lane;
            if (e < ee) {
                float s = ssrc + __ldg(&d_sdst[__ldg(&col[e])]);
                float v = (s > 0.f) ? s : ALPHA * s;
                m = fmaxf(m, v);
            }
        }
        #pragma unroll
        for (int off = 16; off; off >>= 1)
            m = fmaxf(m, __shfl_xor_sync(0xffffffffu, m, off));
        for (int e0 = eb; e0 < ee; e0 += 32) {
            int e = e0 + lane;
            if (e < ee) {
                float s = ssrc + __ldg(&d_sdst[__ldg(&col[e])]);
                float v = (s > 0.f) ? s : ALPHA * s;
                __half hq = __float2half_rn(__expf(v - m));
                d_ew[e] = hq;
                sum += __half2float(hq);
            }
        }
    }
    #pragma unroll
    for (int off = 16; off; off >>= 1)
        sum += __shfl_xor_sync(0xffffffffu, sum, off);
    if (lane == 0) d_inv[gw] = (deg > 0) ? (1.f / sum) : 0.f;
}

// =============================================================================
// K4: windowed segment-MMA aggregation.  One warp = 16 consecutive nodes.
// Sweep the window's edges in contiguous 16-edge batches; 3-stage cp.async
// pipeline; A[r][k] = wq[k] * (row[k] == n0+r); D rows = 16 nodes.
// =============================================================================
#define PIPE 3
__global__ __launch_bounds__(128) void agg_kernel(const int* __restrict__ row,
                                                  const int* __restrict__ col,
                                                  float* __restrict__ out) {
    __shared__ __align__(16) __half s_tile[4][PIPE][16 * F];   // 48 KB
    const int warp = threadIdx.x >> 5;
    const int lane = threadIdx.x & 31;
    const int gw   = (blockIdx.x * blockDim.x + threadIdx.x) >> 5;
    if (gw >= NW) return;

    const int n0 = gw * 16;
    const int eb = d_rowptr[n0];
    const int ee = d_rowptr[n0 + 16];
    const int nb = (ee - eb + 15) >> 4;

    unsigned smb[PIPE];
    #pragma unroll
    for (int s = 0; s < PIPE; ++s) smb[s] = s2u(s_tile[warp][s]);

    const char* __restrict__ hwb = reinterpret_cast<const char*>(d_hwh);
    const int gsl  = lane & 15;
    const int klh  = lane >> 4;
    const int r0   = lane >> 2;
    const int tig  = lane & 3;
    const int kidx = ((lane >> 3) & 1) * 8 + (lane & 7);
    const int joff = lane >> 4;
    const int abs0 = n0 + r0, abs1 = abs0 + 8;
    const int k0 = tig * 2, k1 = k0 + 1, k8 = k0 + 8, k9 = k0 + 9;

    float c[16][4];
    #pragma unroll
    for (int j = 0; j < 16; ++j)
        #pragma unroll
        for (int q = 0; q < 4; ++q) c[j][q] = 0.f;

    auto issue = [&](int b, unsigned dstb) {
        const int e   = eb + b * 16 + gsl;
        const int rem = ee - (eb + b * 16);
        int cc = 0;
        if (e < ee) cc = __ldg(&col[e]);
        #pragma unroll
        for (int it = 0; it < 8; ++it) {
            int kl  = klh + 2 * it;
            int cck = __shfl_sync(0xffffffffu, cc, kl);
            int sz  = (kl < rem) ? 16 : 0;
            unsigned dst = dstb + (unsigned)((kl * 16 + (gsl ^ (kl & 7))) * 16);
            cp16(dst, hwb + ((long long)cck * 256 + gsl * 16), sz);
        }
        cp_commit();
    };

    if (nb > 0) issue(0, smb[0]);
    if (nb > 1) issue(1, smb[1]);

    int scur = 0;                // b % PIPE
    for (int b = 0; b < nb; ++b) {
        if (b + 2 < nb) {
            int sn = scur + 2; if (sn >= PIPE) sn -= PIPE;
            issue(b + 2, smb[sn]);
            cp_wait2();
        } else {
            cp_wait0();
        }
        __syncwarp();

        // A fragment from row/ew (coalesced, L1/L2 hot)
        const int e = eb + b * 16 + gsl;
        int rv = -1; unsigned wv = 0;
        if (e < ee) {
            rv = __ldg(&row[e]);
            wv = (unsigned)*reinterpret_cast<const unsigned short*>(&d_ew[e]);
        }
        int rk0 = __shfl_sync(0xffffffffu, rv, k0);
        int rk1 = __shfl_sync(0xffffffffu, rv, k1);
        int rk8 = __shfl_sync(0xffffffffu, rv, k8);
        int rk9 = __shfl_sync(0xffffffffu, rv, k9);
        unsigned wk0 = __shfl_sync(0xffffffffu, wv, k0);
        unsigned wk1 = __shfl_sync(0xffffffffu, wv, k1);
        unsigned wk8 = __shfl_sync(0xffffffffu, wv, k8);
        unsigned wk9 = __shfl_sync(0xffffffffu, wv, k9);
        unsigned af[4];
        af[0] = (rk0 == abs0 ? wk0 : 0u) | ((rk1 == abs0 ? wk1 : 0u) << 16);
        af[1] = (rk0 == abs1 ? wk0 : 0u) | ((rk1 == abs1 ? wk1 : 0u) << 16);
        af[2] = (rk8 == abs0 ? wk8 : 0u) | ((rk9 == abs0 ? wk9 : 0u) << 16);
        af[3] = (rk8 == abs1 ? wk8 : 0u) | ((rk9 == abs1 ? wk9 : 0u) << 16);

        const unsigned smc = smb[scur];
        #pragma unroll
        for (int j = 0; j < 16; j += 2) {
            unsigned addr = smc + (kidx * 16 + ((j + joff) ^ (kidx & 7))) * 16;
            unsigned b0, b1, b2, b3;
            ldsm_x4_t(b0, b1, b2, b3, addr);
            mma16816(c[j],     af, b0, b1);
            mma16816(c[j + 1], af, b2, b3);
        }
        __syncwarp();
        if (++scur == PIPE) scur = 0;
    }

    // ---- epilogue: D -> smem staging -> normalized elu output ----------------
    cp_wait0();
    __syncwarp();
    float* stg = reinterpret_cast<float*>(s_tile[warp][0]);   // 8 KB of 12 KB
    #pragma unroll
    for (int j = 0; j < 16; ++j) {
        int f0 = j * 8 + tig * 2;
        *reinterpret_cast<float2*>(&stg[r0 * 128 + f0]) =
            make_float2(c[j][0], c[j][1]);
        *reinterpret_cast<float2*>(&stg[(r0 + 8) * 128 + f0]) =
            make_float2(c[j][2], c[j][3]);
    }
    __syncwarp();
    #pragma unroll 4
    for (int rr = 0; rr < 16; ++rr) {
        const int n = n0 + rr;
        const float inv = d_inv[n];
        float4 v = reinterpret_cast<float4*>(stg)[rr * 32 + lane];
        float4 o; float x;
        x = v.x * inv; o.x = (x > 0.f) ? x : expm1f(x);
        x = v.y * inv; o.y = (x > 0.f) ? x : expm1f(x);
        x = v.z * inv; o.z = (x > 0.f) ? x : expm1f(x);
        x = v.w * inv; o.w = (x > 0.f) ? x : expm1f(x);
        reinterpret_cast<float4*>(out)[n * 32 + lane] = o;
    }
}

// =============================================================================
extern "C" void kernel_launch(void* const* d_in, const int* in_sizes, int n_in,
                              void* d_out, int out_size) {
    const float* h     = (const float*)d_in[0];
    const float* W     = (const float*)d_in[1];
    const float* a_src = (const float*)d_in[2];
    const float* a_dst = (const float*)d_in[3];
    const int*   row   = (const int*)d_in[4];
    const int*   col   = (const int*)d_in[5];
    float*       out   = (float*)d_out;

    prep_kernel<<<17, 256>>>(W, a_src, a_dst);
    hgemm_kernel<<<NPAD / 64, 256>>>(h);
    rowptr_kernel<<<(Ee + 255) / 256, 256>>>(row);
    score_kernel<<<(Nn * 32 + 255) / 256, 256>>>(col);
    agg_kernel<<<(NW * 32 + 127) / 128, 128>>>(row, col, out);
}

// round 11
// speedup vs baseline: 2.1718x; 1.4722x over previous
#include <cuda_runtime.h>
#include <cuda_fp16.h>
#include <math.h>

#define Nn    50000
#define NPAD  50048            // 782 * 64
#define Ee    1600000
#define F     128
#define ALPHA 0.2f

typedef unsigned long long ull;

// ---------------- scratch (static device globals; no allocation) -------------
__device__ __half d_Wh[F * F];        // fp16 copy of W
__device__ __half d_hwh[NPAD * F];    // fp16 hw = h @ W
__device__ float  d_wa_src[F];        // W @ a_src
__device__ float  d_wa_dst[F];        // W @ a_dst
__device__ float  d_ssrc[Nn];
__device__ float  d_sdst[Nn];
__device__ int    d_rowptr[Nn + 1];

// ---------------- PTX helpers ------------------------------------------------
__device__ __forceinline__ unsigned s2u(const void* p) {
    return (unsigned)__cvta_generic_to_shared(p);
}
__device__ __forceinline__ void ldsm_x4(unsigned& r0, unsigned& r1,
                                        unsigned& r2, unsigned& r3, unsigned a) {
    asm volatile("ldmatrix.sync.aligned.m8n8.x4.shared.b16 {%0,%1,%2,%3}, [%4];"
                 : "=r"(r0), "=r"(r1), "=r"(r2), "=r"(r3) : "r"(a));
}
__device__ __forceinline__ void ldsm_x4_t(unsigned& r0, unsigned& r1,
                                          unsigned& r2, unsigned& r3, unsigned a) {
    asm volatile("ldmatrix.sync.aligned.m8n8.x4.trans.shared.b16 {%0,%1,%2,%3}, [%4];"
                 : "=r"(r0), "=r"(r1), "=r"(r2), "=r"(r3) : "r"(a));
}
__device__ __forceinline__ void mma16816(float* c, const unsigned* a,
                                         unsigned b0, unsigned b1) {
    asm volatile(
        "mma.sync.aligned.m16n8k16.row.col.f32.f16.f16.f32 "
        "{%0,%1,%2,%3},{%4,%5,%6,%7},{%8,%9},{%0,%1,%2,%3};"
        : "+f"(c[0]), "+f"(c[1]), "+f"(c[2]), "+f"(c[3])
        : "r"(a[0]), "r"(a[1]), "r"(a[2]), "r"(a[3]), "r"(b0), "r"(b1));
}
__device__ __forceinline__ ull pack2(float x, float y) {
    ull r;
    asm("mov.b64 %0, {%1, %2};" : "=l"(r) : "f"(x), "f"(y));
    return r;
}
__device__ __forceinline__ void unpack2(ull v, float& x, float& y) {
    asm("mov.b64 {%0, %1}, %2;" : "=f"(x), "=f"(y) : "l"(v));
}
__device__ __forceinline__ ull add2(ull a, ull b) {
    ull r;
    asm("add.rn.f32x2 %0, %1, %2;" : "=l"(r) : "l"(a), "l"(b));
    return r;
}
__device__ __forceinline__ ull mul2(ull a, ull b) {
    ull r;
    asm("mul.rn.f32x2 %0, %1, %2;" : "=l"(r) : "l"(a), "l"(b));
    return r;
}

// =============================================================================
// K0: blocks 0..15 convert W -> fp16; block 16: wa_src/wa_dst = W @ a
// =============================================================================
__global__ void prep_kernel(const float* __restrict__ W,
                            const float* __restrict__ a_src,
                            const float* __restrict__ a_dst) {
    const int b = blockIdx.x, t = threadIdx.x;
    if (b < 16) {
        int base = b * 1024 + t * 4;
        float4 v = __ldg(&reinterpret_cast<const float4*>(W)[base >> 2]);
        __half2 p0 = __float22half2_rn(make_float2(v.x, v.y));
        __half2 p1 = __float22half2_rn(make_float2(v.z, v.w));
        uint2 u;
        u.x = *reinterpret_cast<unsigned*>(&p0);
        u.y = *reinterpret_cast<unsigned*>(&p1);
        reinterpret_cast<uint2*>(d_Wh)[base >> 2] = u;
    } else {
        const int w = t >> 5, lane = t & 31;
        float4 a4 = __ldg(&reinterpret_cast<const float4*>(a_src)[lane]);
        float4 d4 = __ldg(&reinterpret_cast<const float4*>(a_dst)[lane]);
        for (int r = w; r < F; r += 8) {
            float4 wv = __ldg(&reinterpret_cast<const float4*>(W)[r * 32 + lane]);
            float ps = wv.x * a4.x + wv.y * a4.y + wv.z * a4.z + wv.w * a4.w;
            float pd = wv.x * d4.x + wv.y * d4.y + wv.z * d4.z + wv.w * d4.w;
            #pragma unroll
            for (int off = 16; off; off >>= 1) {
                ps += __shfl_xor_sync(0xffffffffu, ps, off);
                pd += __shfl_xor_sync(0xffffffffu, pd, off);
            }
            if (lane == 0) { d_wa_src[r] = ps; d_wa_dst[r] = pd; }
        }
    }
}

// =============================================================================
// K1: fused hw = fp16(h) @ fp16(W) (mma.sync) + exact fp32 scores
// =============================================================================
__global__ __launch_bounds__(256) void hgemm_kernel(const float* __restrict__ h) {
    __shared__ __align__(16) __half As[64 * F];    // 16 KB
    __shared__ __align__(16) __half Bs[F * F];     // 32 KB

    const int t       = threadIdx.x;
    const int rowBase = blockIdx.x * 64;
    const int lane    = t & 31;
    const int wid     = t >> 5;
    const int wm      = wid >> 2;
    const int wn      = wid & 3;

    {
        const int r   = t >> 2;
        const int seg = t & 3;
        const int gr  = rowBase + r;
        const bool ok = gr < Nn;
        const float4* __restrict__ h4 = reinterpret_cast<const float4*>(h);
        const float4* __restrict__ ws4 = reinterpret_cast<const float4*>(d_wa_src);
        const float4* __restrict__ wd4 = reinterpret_cast<const float4*>(d_wa_dst);
        uint4* __restrict__ As4 = reinterpret_cast<uint4*>(As);

        float ps = 0.f, pd = 0.f;
        #pragma unroll
        for (int j = 0; j < 8; j += 2) {
            float4 v0 = ok ? __ldg(&h4[gr * 32 + seg * 8 + j])     : make_float4(0,0,0,0);
            float4 v1 = ok ? __ldg(&h4[gr * 32 + seg * 8 + j + 1]) : make_float4(0,0,0,0);
            float4 s0 = ws4[seg * 8 + j],     s1 = ws4[seg * 8 + j + 1];
            float4 q0 = wd4[seg * 8 + j],     q1 = wd4[seg * 8 + j + 1];
            ps += v0.x*s0.x + v0.y*s0.y + v0.z*s0.z + v0.w*s0.w
                + v1.x*s1.x + v1.y*s1.y + v1.z*s1.z + v1.w*s1.w;
            pd += v0.x*q0.x + v0.y*q0.y + v0.z*q0.z + v0.w*q0.w
                + v1.x*q1.x + v1.y*q1.y + v1.z*q1.z + v1.w*q1.w;
            __half2 p0 = __float22half2_rn(make_float2(v0.x, v0.y));
            __half2 p1 = __float22half2_rn(make_float2(v0.z, v0.w));
            __half2 p2 = __float22half2_rn(make_float2(v1.x, v1.y));
            __half2 p3 = __float22half2_rn(make_float2(v1.z, v1.w));
            uint4 u;
            u.x = *reinterpret_cast<unsigned*>(&p0);
            u.y = *reinterpret_cast<unsigned*>(&p1);
            u.z = *reinterpret_cast<unsigned*>(&p2);
            u.w = *reinterpret_cast<unsigned*>(&p3);
            int g = seg * 4 + (j >> 1);
            As4[r * 16 + (g ^ (r & 7))] = u;
        }
        ps += __shfl_xor_sync(0xffffffffu, ps, 1);
        ps += __shfl_xor_sync(0xffffffffu, ps, 2);
        pd += __shfl_xor_sync(0xffffffffu, pd, 1);
        pd += __shfl_xor_sync(0xffffffffu, pd, 2);
        if (seg == 0 && ok) { d_ssrc[gr] = ps; d_sdst[gr] = pd; }
    }
    {
        const uint4* __restrict__ Wh4 = reinterpret_cast<const uint4*>(d_Wh);
        uint4* __restrict__ Bs4 = reinterpret_cast<uint4*>(Bs);
        #pragma unroll
        for (int i = 0; i < 8; ++i) {
            int G = i * 256 + t;
            int r = G >> 4, g = G & 15;
            Bs4[r * 16 + (g ^ (r & 7))] = Wh4[G];
        }
    }
    __syncthreads();

    const unsigned Ab = s2u(As), Bb = s2u(Bs);
    float c[2][4][4];
    #pragma unroll
    for (int i = 0; i < 2; ++i)
        #pragma unroll
        for (int j = 0; j < 4; ++j)
            #pragma unroll
            for (int q = 0; q < 4; ++q) c[i][j][q] = 0.f;

    #pragma unroll
    for (int kk = 0; kk < 8; ++kk) {
        unsigned a[2][4], b[2][4];
        #pragma unroll
        for (int i = 0; i < 2; ++i) {
            int r = wm * 32 + i * 16 + (lane & 15);
            int g = kk * 2 + (lane >> 4);
            ldsm_x4(a[i][0], a[i][1], a[i][2], a[i][3],
                    Ab + (r * 16 + (g ^ (r & 7))) * 16);
        }
        #pragma unroll
        for (int jp = 0; jp < 2; ++jp) {
            int kr = kk * 16 + (lane & 15);
            int g  = wn * 4 + jp * 2 + (lane >> 4);
            ldsm_x4_t(b[jp][0], b[jp][1], b[jp][2], b[jp][3],
                      Bb + (kr * 16 + (g ^ (kr & 7))) * 16);
        }
        #pragma unroll
        for (int i = 0; i < 2; ++i)
            #pragma unroll
            for (int j = 0; j < 4; ++j)
                mma16816(c[i][j], a[i], b[j >> 1][(j & 1) * 2],
                         b[j >> 1][(j & 1) * 2 + 1]);
    }

    const int g  = lane >> 2;
    const int cp = (lane & 3) * 2;
    #pragma unroll
    for (int i = 0; i < 2; ++i)
        #pragma unroll
        for (int j = 0; j < 4; ++j) {
            int gr = rowBase + wm * 32 + i * 16 + g;
            int gc = wn * 32 + j * 8 + cp;
            __half2 lo = __float22half2_rn(make_float2(c[i][j][0], c[i][j][1]));
            __half2 hi = __float22half2_rn(make_float2(c[i][j][2], c[i][j][3]));
            *reinterpret_cast<__half2*>(&d_hwh[gr * F + gc])       = lo;
            *reinterpret_cast<__half2*>(&d_hwh[(gr + 8) * F + gc]) = hi;
        }
}

// =============================================================================
// K2: edge-parallel rowptr from sorted row
// =============================================================================
__global__ void rowptr_kernel(const int* __restrict__ row) {
    int i = blockIdx.x * blockDim.x + threadIdx.x;
    if (i >= Ee) return;
    int a = __ldg(&row[i]);
    int b = (i + 1 < Ee) ? __ldg(&row[i + 1]) : Nn;
    for (int r = a + 1; r <= b; ++r) d_rowptr[r] = i + 1;
    if (i == 0)
        for (int r = 0; r <= a; ++r) d_rowptr[r] = 0;
}

// =============================================================================
// K3: warp-per-node: online softmax fused with fp16-ACCUMULATE gather.
// Inner: one shfl of packed (wq<<16|col), LDG.128, 4x HFMA2; flush the fp16
// partial into packed-f32x2 master accumulators every 8 edges.
// =============================================================================
__global__ __launch_bounds__(256) void edge_kernel(const int* __restrict__ col,
                                                   float* __restrict__ out) {
    const int gw   = (blockIdx.x * blockDim.x + threadIdx.x) >> 5;
    const int lane = threadIdx.x & 31;
    if (gw >= Nn) return;
    const int   eb   = d_rowptr[gw];
    const int   ee   = d_rowptr[gw + 1];
    const float ssrc = d_ssrc[gw];

    const uint4* __restrict__ hw4 = reinterpret_cast<const uint4*>(d_hwh);
    const int half_id = lane >> 4;
    const int fg      = lane & 15;

    float m = -1e30f, sum = 0.f;
    ull facc[4] = {0ull, 0ull, 0ull, 0ull};

    const __half2 hz = __float2half2_rn(0.f);

    for (int e0 = eb; e0 < ee; e0 += 32) {
        const int e   = e0 + lane;
        const int cnt = min(32, ee - e0);

        // ---- per-lane score + online softmax state ---------------------------
        float v = -1e30f; int cl = 0;
        if (e < ee) {
            cl = __ldg(&col[e]);
            float s = ssrc + __ldg(&d_sdst[cl]);
            v = (s > 0.f) ? s : ALPHA * s;
        }
        float bm = v;
        #pragma unroll
        for (int off = 16; off; off >>= 1)
            bm = fmaxf(bm, __shfl_xor_sync(0xffffffffu, bm, off));
        if (bm > m) {
            const float sc = __expf(m - bm);
            sum *= sc;
            const ull sc2 = pack2(sc, sc);
            facc[0] = mul2(facc[0], sc2);
            facc[1] = mul2(facc[1], sc2);
            facc[2] = mul2(facc[2], sc2);
            facc[3] = mul2(facc[3], sc2);
            m = bm;
        }
        const __half   wh = __float2half_rn(__expf(v - m));
        const unsigned wq = (unsigned)__half_as_ushort(wh);
        float bs = __half2float(wh);                 // quantized weight -> sum
        #pragma unroll
        for (int off = 16; off; off >>= 1)
            bs += __shfl_xor_sync(0xffffffffu, bs, off);
        sum += bs;

        // ---- gather with fp16 accumulate -------------------------------------
        const unsigned pk = (wq << 16) | (unsigned)cl;    // col < 65536
        __half2 hacc0 = hz, hacc1 = hz, hacc2 = hz, hacc3 = hz;

        #pragma unroll 4
        for (int j = 0; j < cnt; j += 2) {
            const unsigned p  = __shfl_sync(0xffffffffu, pk, j + half_id);
            const __half2  w2 = __half2half2(__ushort_as_half((unsigned short)(p >> 16)));
            const uint4    q  = __ldg(&hw4[(p & 0xffffu) * 16 + fg]);
            hacc0 = __hfma2(*reinterpret_cast<const __half2*>(&q.x), w2, hacc0);
            hacc1 = __hfma2(*reinterpret_cast<const __half2*>(&q.y), w2, hacc1);
            hacc2 = __hfma2(*reinterpret_cast<const __half2*>(&q.z), w2, hacc2);
            hacc3 = __hfma2(*reinterpret_cast<const __half2*>(&q.w), w2, hacc3);
            if ((j & 7) == 6) {                     // flush every 8 edges
                float2 f0 = __half22float2(hacc0);
                float2 f1 = __half22float2(hacc1);
                float2 f2 = __half22float2(hacc2);
                float2 f3 = __half22float2(hacc3);
                facc[0] = add2(facc[0], pack2(f0.x, f0.y));
                facc[1] = add2(facc[1], pack2(f1.x, f1.y));
                facc[2] = add2(facc[2], pack2(f2.x, f2.y));
                facc[3] = add2(facc[3], pack2(f3.x, f3.y));
                hacc0 = hz; hacc1 = hz; hacc2 = hz; hacc3 = hz;
            }
        }
        if (cnt & 7) {                              // flush remainder
            float2 f0 = __half22float2(hacc0);
            float2 f1 = __half22float2(hacc1);
            float2 f2 = __half22float2(hacc2);
            float2 f3 = __half22float2(hacc3);
            facc[0] = add2(facc[0], pack2(f0.x, f0.y));
            facc[1] = add2(facc[1], pack2(f1.x, f1.y));
            facc[2] = add2(facc[2], pack2(f2.x, f2.y));
            facc[3] = add2(facc[3], pack2(f3.x, f3.y));
        }
    }

    // ---- merge half-warps, normalize, elu, store -----------------------------
    float a[8];
    unpack2(facc[0], a[0], a[1]);
    unpack2(facc[1], a[2], a[3]);
    unpack2(facc[2], a[4], a[5]);
    unpack2(facc[3], a[6], a[7]);
    #pragma unroll
    for (int f = 0; f < 8; ++f)
        a[f] += __shfl_xor_sync(0xffffffffu, a[f], 16);

    if (lane < 16) {
        const float inv = (ee > eb) ? (1.f / sum) : 0.f;
        float o[8];
        #pragma unroll
        for (int f = 0; f < 8; ++f) {
            float x = a[f] * inv;
            o[f] = (x > 0.f) ? x : expm1f(x);
        }
        float4* op = reinterpret_cast<float4*>(&out[gw * F + fg * 8]);
        op[0] = make_float4(o[0], o[1], o[2], o[3]);
        op[1] = make_float4(o[4], o[5], o[6], o[7]);
    }
}

// =============================================================================
extern "C" void kernel_launch(void* const* d_in, const int* in_sizes, int n_in,
                              void* d_out, int out_size) {
    const float* h     = (const float*)d_in[0];
    const float* W     = (const float*)d_in[1];
    const float* a_src = (const float*)d_in[2];
    const float* a_dst = (const float*)d_in[3];
    const int*   row   = (const int*)d_in[4];
    const int*   col   = (const int*)d_in[5];
    float*       out   = (float*)d_out;

    prep_kernel<<<17, 256>>>(W, a_src, a_dst);
    hgemm_kernel<<<NPAD / 64, 256>>>(h);
    rowptr_kernel<<<(Ee + 255) / 256, 256>>>(row);
    edge_kernel<<<(Nn * 32 + 255) / 256, 256>>>(col, out);
}